// round 11
// baseline (speedup 1.0000x reference)
#include <cuda_runtime.h>
#include <cuda_bf16.h>

#define NMAX 50176
#define LN_EPS 1e-5f

__device__ float g_q[NMAX * 64];
__device__ float g_k[NMAX * 64];
__device__ float g_v[NMAX * 64];

// packed B fragments: [weight(6: wg1,wg2,wq,wk,wv,wo)][j(8)][kt(4)][lane(32)]
__device__ uint4 g_bfragP[6144];
__device__ float g_gram[20];
__device__ float g_pp[384];   // permuted positional params: wx|wy|wz|bp|gp|betap

typedef unsigned long long u64;
typedef unsigned int u32;

__device__ __forceinline__ u32 cvt2bf(float hi, float lo) {
    u32 r;
    asm("cvt.rn.bf16x2.f32 %0, %1, %2;" : "=r"(r) : "f"(hi), "f"(lo));
    return r;
}
__device__ __forceinline__ void bsplit2(float x, float y, u32& hp, u32& lp) {
    hp = cvt2bf(y, x);
    const float hx = __uint_as_float(hp << 16);
    const float hy = __uint_as_float(hp & 0xFFFF0000u);
    lp = cvt2bf(y - hy, x - hx);
}
__device__ __forceinline__ void mma16816(float* d, const u32* a, u32 b0, u32 b1) {
    asm volatile(
        "mma.sync.aligned.m16n8k16.row.col.f32.bf16.bf16.f32 "
        "{%0,%1,%2,%3}, {%4,%5,%6,%7}, {%8,%9}, {%0,%1,%2,%3};"
        : "+f"(d[0]), "+f"(d[1]), "+f"(d[2]), "+f"(d[3])
        : "r"(a[0]), "r"(a[1]), "r"(a[2]), "r"(a[3]), "r"(b0), "r"(b1));
}

struct Geo {
    int id1, id2;
    float rx1, ry1, rz1, rx2, ry2, rz2;
    float mean1, inv1, mean2, inv2;
};

__device__ __forceinline__ void load_geo(
    const int* __restrict__ nbr, const float* __restrict__ points,
    const float* sM, int n, int r1, Geo& g)
{
    g.id1 = __ldg(&nbr[n * 16 + r1]);
    g.id2 = __ldg(&nbr[n * 16 + r1 + 8]);
    const float px = __ldg(&points[n * 3 + 0]);
    const float py = __ldg(&points[n * 3 + 1]);
    const float pz = __ldg(&points[n * 3 + 2]);
    g.rx1 = __ldg(&points[g.id1 * 3 + 0]) - px;
    g.ry1 = __ldg(&points[g.id1 * 3 + 1]) - py;
    g.rz1 = __ldg(&points[g.id1 * 3 + 2]) - pz;
    g.rx2 = __ldg(&points[g.id2 * 3 + 0]) - px;
    g.ry2 = __ldg(&points[g.id2 * 3 + 1]) - py;
    g.rz2 = __ldg(&points[g.id2 * 3 + 2]) - pz;
    {
        const float s1 = fmaf(g.rx1, sM[16], fmaf(g.ry1, sM[17],
                         fmaf(g.rz1, sM[18], sM[19])));
        const float tx = fmaf(g.rx1, sM[0],  fmaf(g.ry1, sM[1],
                         fmaf(g.rz1, sM[2],  sM[3])));
        const float ty = fmaf(g.rx1, sM[4],  fmaf(g.ry1, sM[5],
                         fmaf(g.rz1, sM[6],  sM[7])));
        const float tz = fmaf(g.rx1, sM[8],  fmaf(g.ry1, sM[9],
                         fmaf(g.rz1, sM[10], sM[11])));
        const float tw = fmaf(g.rx1, sM[12], fmaf(g.ry1, sM[13],
                         fmaf(g.rz1, sM[14], sM[15])));
        const float s2 = fmaf(g.rx1, tx, fmaf(g.ry1, ty, fmaf(g.rz1, tz, tw)));
        g.mean1 = s1 * 0.015625f;
        g.inv1 = rsqrtf(s2 * 0.015625f - g.mean1 * g.mean1 + LN_EPS);
    }
    {
        const float s1 = fmaf(g.rx2, sM[16], fmaf(g.ry2, sM[17],
                         fmaf(g.rz2, sM[18], sM[19])));
        const float tx = fmaf(g.rx2, sM[0],  fmaf(g.ry2, sM[1],
                         fmaf(g.rz2, sM[2],  sM[3])));
        const float ty = fmaf(g.rx2, sM[4],  fmaf(g.ry2, sM[5],
                         fmaf(g.rz2, sM[6],  sM[7])));
        const float tz = fmaf(g.rx2, sM[8],  fmaf(g.ry2, sM[9],
                         fmaf(g.rz2, sM[10], sM[11])));
        const float tw = fmaf(g.rx2, sM[12], fmaf(g.ry2, sM[13],
                         fmaf(g.rz2, sM[14], sM[15])));
        const float s2 = fmaf(g.rx2, tx, fmaf(g.ry2, ty, fmaf(g.rz2, tz, tw)));
        g.mean2 = s1 * 0.015625f;
        g.inv2 = rsqrtf(s2 * 0.015625f - g.mean2 * g.mean2 + LN_EPS);
    }
}

// ---------------------------------------------------------------------------
// Init: packed B fragments for 6 weights + permuted pos-params + Gram.
// ---------------------------------------------------------------------------
__global__ void build_kernel(const float* __restrict__ wg1,
                             const float* __restrict__ wg2,
                             const float* __restrict__ wq,
                             const float* __restrict__ wk,
                             const float* __restrict__ wv,
                             const float* __restrict__ wo,
                             const float* __restrict__ wp,
                             const float* __restrict__ bp,
                             const float* __restrict__ gp,
                             const float* __restrict__ betap)
{
    const int t = threadIdx.x;
    if (blockIdx.x < 24) {
        const int e = blockIdx.x * 256 + t;
        const int lane = e & 31;
        const int kt   = (e >> 5) & 3;
        const int j    = (e >> 7) & 7;
        const int wi   = e >> 10;
        const float* Wt[6] = { wg1, wg2, wq, wk, wv, wo };
        const float* W = Wt[wi];
        const int n  = 8 * j + (lane >> 2);
        const int k0 = 16 * kt + 2 * (lane & 3);
        u32 h0, l0, h1, l1;
        bsplit2(W[k0 * 64 + n],       W[(k0 + 1) * 64 + n], h0, l0);
        bsplit2(W[(k0 + 8) * 64 + n], W[(k0 + 9) * 64 + n], h1, l1);
        g_bfragP[e] = make_uint4(h0, h1, l0, l1);
    } else {
        if (t < 64) {
            const int p = t;
            const int kt = p >> 4, q = (p >> 2) & 3, i = p & 3;
            const int tc = 16 * kt + ((i < 2) ? (2 * q + i) : (6 + 2 * q + i));
            g_pp[0 * 64 + p] = wp[tc];
            g_pp[1 * 64 + p] = wp[64 + tc];
            g_pp[2 * 64 + p] = wp[128 + tc];
            g_pp[3 * 64 + p] = bp[tc];
            g_pp[4 * 64 + p] = gp[tc];
            g_pp[5 * 64 + p] = betap[tc];
        } else if (t < 84) {
            const int tt = t - 64;
            if (tt < 16) {
                const int a = tt >> 2, b = tt & 3;
                const float* ra = (a < 3) ? (wp + a * 64) : bp;
                const float* rb = (b < 3) ? (wp + b * 64) : bp;
                float s = 0.f;
                for (int c = 0; c < 64; c++) s += ra[c] * rb[c];
                g_gram[tt] = s;
            } else {
                const int a = tt - 16;
                const float* ra = (a < 3) ? (wp + a * 64) : bp;
                float s = 0.f;
                for (int c = 0; c < 64; c++) s += ra[c];
                g_gram[tt] = s;
            }
        }
    }
}

// ---------------------------------------------------------------------------
// Kernel A: q/k/v via mma.sync bf16-split; K-PERMUTED output layout.
// ---------------------------------------------------------------------------
__global__ __launch_bounds__(128, 4) void qkv_mma_kernel(
    const float* __restrict__ feat, int N,
    const float* __restrict__ bq, const float* __restrict__ bk,
    const float* __restrict__ bv)
{
    const int t = threadIdx.x;
    const int lane = t & 31;
    const int warp = t >> 5;
    const int qd = lane & 3;
    const int base = 2 * qd;
    const int r1 = lane >> 2;

    const int row0 = (blockIdx.x * 4 + warp) * 16;
    const int rowA = row0 + r1;
    const int rowB = row0 + r1 + 8;
    const int rowAc = (rowA < N) ? rowA : N - 1;
    const int rowBc = (rowB < N) ? rowB : N - 1;

    u32 aHi[16], aLo[16];
#pragma unroll
    for (int m = 0; m < 8; m++) {
        const int c = 8 * m + base;
        const float2 fA = *(const float2*)(feat + rowAc * 64 + c);
        const float2 fB = *(const float2*)(feat + rowBc * 64 + c);
        const int kt = m >> 1;
        const int ro = (m & 1) << 1;
        bsplit2(fA.x, fA.y, aHi[kt * 4 + ro],     aLo[kt * 4 + ro]);
        bsplit2(fB.x, fB.y, aHi[kt * 4 + ro + 1], aLo[kt * 4 + ro + 1]);
    }

    const float* Bs[3] = { bq, bk, bv };
    float* Gs[3] = { g_q, g_k, g_v };
#pragma unroll 1
    for (int wi = 0; wi < 3; wi++) {
        const uint4* fr = g_bfragP + (2 + wi) * 1024;
        float d[8][4];
#pragma unroll
        for (int j = 0; j < 8; j++)
#pragma unroll
            for (int i = 0; i < 4; i++) d[j][i] = 0.f;
#pragma unroll
        for (int kt = 0; kt < 4; kt++) {
#pragma unroll
            for (int j = 0; j < 8; j++) {
                const uint4 e = __ldg(&fr[j * 128 + kt * 32 + lane]);
                mma16816(d[j], &aHi[kt * 4], e.x, e.y);
                mma16816(d[j], &aLo[kt * 4], e.x, e.y);
                mma16816(d[j], &aHi[kt * 4], e.z, e.w);
            }
        }
        float* G = Gs[wi];
        const float* B = Bs[wi];
#pragma unroll
        for (int j = 0; j < 8; j++) {
            const float2 b2 = __ldg((const float2*)(B + 8 * j + base));
            const int P = 16 * (j >> 1) + 4 * qd + ((j & 1) << 1);
            if (rowA < N)
                *(float2*)(G + rowA * 64 + P) =
                    make_float2(d[j][0] + b2.x, d[j][1] + b2.y);
            if (rowB < N)
                *(float2*)(G + rowB * 64 + P) =
                    make_float2(d[j][2] + b2.x, d[j][3] + b2.y);
        }
    }
}

// ---------------------------------------------------------------------------
// Kernel B: 2 points per warp, software-pipelined geometry prefetch.
// 8 points per CTA. 5 CTA/SM.
// ---------------------------------------------------------------------------
#define GVS 66
#define LWS 66

__global__ __launch_bounds__(128, 5) void pt_mma_kernel(
    const float* __restrict__ points, const float* __restrict__ feat,
    const int* __restrict__ nbr, int N,
    const float* __restrict__ bg1, const float* __restrict__ gg,
    const float* __restrict__ betag,
    const float* __restrict__ bo,
    float* __restrict__ out)
{
    __shared__ float gvs[4 * 16 * GVS];   // 16896 B
    __shared__ float lw[4][16][LWS];      // 16896 B
    __shared__ float mout[8][LWS];        // 2112 B
    __shared__ float spp[404];            // 1616 B: g_pp (384) + gram (20)

    const int t = threadIdx.x;
    const int lane = t & 31;
    const int warp = t >> 5;

    for (int i = t; i < 404; i += 128)
        spp[i] = (i < 384) ? g_pp[i] : g_gram[i - 384];
    __syncthreads();
    const float* sM = spp + 384;

    const int qd = lane & 3;
    const int base = 2 * qd;
    const int r1 = lane >> 2;
    float* mygv = gvs + warp * 16 * GVS;

    // warp handles points n(0)=blk*8+warp, n(1)=blk*8+4+warp
    int np[2];
    np[0] = blockIdx.x * 8 + warp;
    np[1] = blockIdx.x * 8 + 4 + warp;
    if (np[0] >= N) np[0] = N - 1;
    if (np[1] >= N) np[1] = N - 1;

    Geo geo[2];
    load_geo(nbr, points, sM, np[0], r1, geo[0]);

#pragma unroll 1
    for (int it = 0; it < 2; it++) {
        const int n = np[it];
        const Geo g = geo[it];

        // ---- gather (float4, permuted) + positional LN/relu ----
        u32 aHi[16], aLo[16];
#pragma unroll
        for (int kt = 0; kt < 4; kt++) {
            const int pc = 16 * kt + 4 * qd;
            const float4 q4  = *(const float4*)(g_q + n * 64 + pc);
            const float4 k1v = *(const float4*)(g_k + g.id1 * 64 + pc);
            const float4 k2v = *(const float4*)(g_k + g.id2 * 64 + pc);
            const float4 v1v = *(const float4*)(g_v + g.id1 * 64 + pc);
            const float4 v2v = *(const float4*)(g_v + g.id2 * 64 + pc);
            const float4 wxv = *(const float4*)(spp + 0 * 64 + pc);
            const float4 wyv = *(const float4*)(spp + 1 * 64 + pc);
            const float4 wzv = *(const float4*)(spp + 2 * 64 + pc);
            const float4 bpv = *(const float4*)(spp + 3 * 64 + pc);
            const float4 gpv = *(const float4*)(spp + 4 * 64 + pc);
            const float4 bev = *(const float4*)(spp + 5 * 64 + pc);

            float vA[4], vB[4];
            {
                const float* wx = &wxv.x; const float* wy = &wyv.x;
                const float* wz = &wzv.x; const float* bb = &bpv.x;
                const float* gp2 = &gpv.x; const float* be = &bev.x;
#pragma unroll
                for (int i = 0; i < 4; i++) {
                    const float pA = fmaf(g.rx1, wx[i], fmaf(g.ry1, wy[i],
                                     fmaf(g.rz1, wz[i], bb[i])));
                    const float pB = fmaf(g.rx2, wx[i], fmaf(g.ry2, wy[i],
                                     fmaf(g.rz2, wz[i], bb[i])));
                    vA[i] = fmaxf(fmaf((pA - g.mean1) * g.inv1, gp2[i], be[i]), 0.f);
                    vB[i] = fmaxf(fmaf((pB - g.mean2) * g.inv2, gp2[i], be[i]), 0.f);
                }
            }

            bsplit2(q4.x - k1v.x + vA[0], q4.y - k1v.y + vA[1],
                    aHi[kt * 4 + 0], aLo[kt * 4 + 0]);
            bsplit2(q4.x - k2v.x + vB[0], q4.y - k2v.y + vB[1],
                    aHi[kt * 4 + 1], aLo[kt * 4 + 1]);
            bsplit2(q4.z - k1v.z + vA[2], q4.w - k1v.w + vA[3],
                    aHi[kt * 4 + 2], aLo[kt * 4 + 2]);
            bsplit2(q4.z - k2v.z + vB[2], q4.w - k2v.w + vB[3],
                    aHi[kt * 4 + 3], aLo[kt * 4 + 3]);

            *(float2*)(mygv + r1 * GVS + 16 * kt + base) =
                make_float2(v1v.x + vA[0], v1v.y + vA[1]);
            *(float2*)(mygv + (r1 + 8) * GVS + 16 * kt + base) =
                make_float2(v2v.x + vB[0], v2v.y + vB[1]);
            *(float2*)(mygv + r1 * GVS + 16 * kt + 8 + base) =
                make_float2(v1v.z + vA[2], v1v.w + vA[3]);
            *(float2*)(mygv + (r1 + 8) * GVS + 16 * kt + 8 + base) =
                make_float2(v2v.z + vB[2], v2v.w + vB[3]);
        }

        // prefetch next point's geometry — overlaps GEMM1/LN/GEMM2 latency
        if (it == 0) load_geo(nbr, points, sM, np[1], r1, geo[1]);

        // ---- GEMM1 ----
        float d[8][4];
#pragma unroll
        for (int j = 0; j < 8; j++)
#pragma unroll
            for (int i = 0; i < 4; i++) d[j][i] = 0.f;
#pragma unroll
        for (int kt = 0; kt < 4; kt++) {
#pragma unroll
            for (int j = 0; j < 8; j++) {
                const uint4 e = __ldg(&g_bfragP[j * 128 + kt * 32 + lane]);
                mma16816(d[j], &aHi[kt * 4], e.x, e.y);
                mma16816(d[j], &aLo[kt * 4], e.x, e.y);
                mma16816(d[j], &aHi[kt * 4], e.z, e.w);
            }
        }

        // ---- LN + relu over rows (4-lane groups) ----
        {
            float s1a = 0.f, s2a = 0.f, s1b = 0.f, s2b = 0.f;
#pragma unroll
            for (int j = 0; j < 8; j++) {
                const float2 bg = __ldg((const float2*)(bg1 + 8 * j + base));
                d[j][0] += bg.x; d[j][1] += bg.y;
                d[j][2] += bg.x; d[j][3] += bg.y;
                s1a += d[j][0] + d[j][1];
                s2a += d[j][0] * d[j][0] + d[j][1] * d[j][1];
                s1b += d[j][2] + d[j][3];
                s2b += d[j][2] * d[j][2] + d[j][3] * d[j][3];
            }
#pragma unroll
            for (int off = 1; off <= 2; off <<= 1) {
                s1a += __shfl_xor_sync(0xffffffffu, s1a, off);
                s2a += __shfl_xor_sync(0xffffffffu, s2a, off);
                s1b += __shfl_xor_sync(0xffffffffu, s1b, off);
                s2b += __shfl_xor_sync(0xffffffffu, s2b, off);
            }
            const float m1 = s1a * 0.015625f;
            const float i1 = rsqrtf(s2a * 0.015625f - m1 * m1 + LN_EPS);
            const float m2 = s1b * 0.015625f;
            const float i2 = rsqrtf(s2b * 0.015625f - m2 * m2 + LN_EPS);
#pragma unroll
            for (int j = 0; j < 8; j++) {
                const int c = 8 * j + base;
                const float2 gA = __ldg((const float2*)(gg + c));
                const float2 bA = __ldg((const float2*)(betag + c));
                d[j][0] = fmaxf(fmaf((d[j][0] - m1) * i1, gA.x, bA.x), 0.f);
                d[j][1] = fmaxf(fmaf((d[j][1] - m1) * i1, gA.y, bA.y), 0.f);
                d[j][2] = fmaxf(fmaf((d[j][2] - m2) * i2, gA.x, bA.x), 0.f);
                d[j][3] = fmaxf(fmaf((d[j][3] - m2) * i2, gA.y, bA.y), 0.f);
            }
        }

        // ---- repack h into A fragments ----
#pragma unroll
        for (int kt = 0; kt < 4; kt++) {
            bsplit2(d[2 * kt][0],     d[2 * kt][1],     aHi[kt * 4 + 0], aLo[kt * 4 + 0]);
            bsplit2(d[2 * kt][2],     d[2 * kt][3],     aHi[kt * 4 + 1], aLo[kt * 4 + 1]);
            bsplit2(d[2 * kt + 1][0], d[2 * kt + 1][1], aHi[kt * 4 + 2], aLo[kt * 4 + 2]);
            bsplit2(d[2 * kt + 1][2], d[2 * kt + 1][3], aHi[kt * 4 + 3], aLo[kt * 4 + 3]);
        }

        // ---- GEMM2: logits ----
#pragma unroll
        for (int j = 0; j < 8; j++)
#pragma unroll
            for (int i = 0; i < 4; i++) d[j][i] = 0.f;
#pragma unroll
        for (int kt = 0; kt < 4; kt++) {
#pragma unroll
            for (int j = 0; j < 8; j++) {
                const uint4 e = __ldg(&g_bfragP[1024 + j * 128 + kt * 32 + lane]);
                mma16816(d[j], &aHi[kt * 4], e.x, e.y);
                mma16816(d[j], &aLo[kt * 4], e.x, e.y);
                mma16816(d[j], &aHi[kt * 4], e.z, e.w);
            }
        }

        // ---- stage logits; column softmax ----
#pragma unroll
        for (int j = 0; j < 8; j++) {
            *(float2*)&lw[warp][r1][8 * j + base]     = make_float2(d[j][0], d[j][1]);
            *(float2*)&lw[warp][r1 + 8][8 * j + base] = make_float2(d[j][2], d[j][3]);
        }
        __syncwarp();
#pragma unroll
        for (int cc = 0; cc < 2; cc++) {
            const int c = lane + 32 * cc;
            float mx = -3.4e38f;
#pragma unroll
            for (int k = 0; k < 16; k++) mx = fmaxf(mx, lw[warp][k][c]);
            float s = 0.f, o = 0.f;
#pragma unroll
            for (int k = 0; k < 16; k++) {
                const float e = __expf(lw[warp][k][c] - mx);
                s += e;
                o = fmaf(e, mygv[k * GVS + c], o);
            }
            mout[warp + 4 * it][c] = __fdividef(o, s);
        }
        __syncwarp();
    }
    __syncthreads();

    // ---- final GEMM via mma: out = mout @ wo + bo + residual ----
    // A rows 8..15 structurally zero.
    {
        u32 aH2[16], aL2[16];
#pragma unroll
        for (int m = 0; m < 8; m++) {
            const int kt = m >> 1;
            const int ro = (m & 1) << 1;
            const float2 fA = *(const float2*)&mout[r1][8 * m + base];
            bsplit2(fA.x, fA.y, aH2[kt * 4 + ro], aL2[kt * 4 + ro]);
            aH2[kt * 4 + ro + 1] = 0u; aL2[kt * 4 + ro + 1] = 0u;
        }
        float dd[2][4];
#pragma unroll
        for (int jj = 0; jj < 2; jj++)
#pragma unroll
            for (int i = 0; i < 4; i++) dd[jj][i] = 0.f;
#pragma unroll
        for (int kt = 0; kt < 4; kt++) {
#pragma unroll
            for (int jj = 0; jj < 2; jj++) {
                const int j = 2 * warp + jj;
                const uint4 e = __ldg(&g_bfragP[5120 + j * 128 + kt * 32 + lane]);
                mma16816(dd[jj], &aH2[kt * 4], e.x, e.y);
                mma16816(dd[jj], &aL2[kt * 4], e.x, e.y);
                mma16816(dd[jj], &aH2[kt * 4], e.z, e.w);
            }
        }
        {
            const int n3 = blockIdx.x * 8 + r1;
            if (n3 < N) {
#pragma unroll
                for (int jj = 0; jj < 2; jj++) {
                    const int c = 8 * (2 * warp + jj) + base;
                    const float2 b2 = __ldg((const float2*)(bo + c));
                    const float2 f2 = *(const float2*)(feat + n3 * 64 + c);
                    *(float2*)(out + n3 * 64 + c) =
                        make_float2(dd[jj][0] + b2.x + f2.x,
                                    dd[jj][1] + b2.y + f2.y);
                }
            }
        }
    }
}

// ---------------------------------------------------------------------------
extern "C" void kernel_launch(void* const* d_in, const int* in_sizes, int n_in,
                              void* d_out, int out_size)
{
    const float* points = (const float*)d_in[0];
    const float* feat   = (const float*)d_in[1];
    const int*   nbr    = (const int*)  d_in[2];
    const float* wq     = (const float*)d_in[3];
    const float* bq     = (const float*)d_in[4];
    const float* wk     = (const float*)d_in[5];
    const float* bk     = (const float*)d_in[6];
    const float* wv     = (const float*)d_in[7];
    const float* bv     = (const float*)d_in[8];
    const float* wp     = (const float*)d_in[9];
    const float* bp     = (const float*)d_in[10];
    const float* gp     = (const float*)d_in[11];
    const float* betap  = (const float*)d_in[12];
    const float* wg1    = (const float*)d_in[13];
    const float* bg1    = (const float*)d_in[14];
    const float* gg     = (const float*)d_in[15];
    const float* betag  = (const float*)d_in[16];
    const float* wg2    = (const float*)d_in[17];
    const float* bg2    = (const float*)d_in[18];
    const float* wo     = (const float*)d_in[19];
    const float* bo     = (const float*)d_in[20];
    float* out = (float*)d_out;
    (void)bg2;

    const int N = in_sizes[0] / 3;

    build_kernel<<<25, 256>>>(wg1, wg2, wq, wk, wv, wo, wp, bp, gp, betap);
    qkv_mma_kernel<<<(N + 63) / 64, 128>>>(feat, N, bq, bk, bv);
    pt_mma_kernel<<<(N + 7) / 8, 128>>>(points, feat, nbr, N,
                                        bg1, gg, betag, bo, out);
}

// round 12
// speedup vs baseline: 1.0204x; 1.0204x over previous
#include <cuda_runtime.h>
#include <cuda_bf16.h>

#define NMAX 50176
#define LN_EPS 1e-5f

__device__ float g_q[NMAX * 64];
__device__ float g_k[NMAX * 64];
__device__ float g_v[NMAX * 64];
__device__ float g_mout[NMAX * 64];

// packed B fragments: [weight(6: wg1,wg2,wq,wk,wv,wo)][j(8)][kt(4)][lane(32)]
__device__ uint4 g_bfragP[6144];
__device__ float g_gram[20];
__device__ float g_pp[384];   // permuted positional params: wx|wy|wz|bp|gp|betap

typedef unsigned long long u64;
typedef unsigned int u32;

__device__ __forceinline__ u32 cvt2bf(float hi, float lo) {
    u32 r;
    asm("cvt.rn.bf16x2.f32 %0, %1, %2;" : "=r"(r) : "f"(hi), "f"(lo));
    return r;
}
__device__ __forceinline__ void bsplit2(float x, float y, u32& hp, u32& lp) {
    hp = cvt2bf(y, x);
    const float hx = __uint_as_float(hp << 16);
    const float hy = __uint_as_float(hp & 0xFFFF0000u);
    lp = cvt2bf(y - hy, x - hx);
}
__device__ __forceinline__ void mma16816(float* d, const u32* a, u32 b0, u32 b1) {
    asm volatile(
        "mma.sync.aligned.m16n8k16.row.col.f32.bf16.bf16.f32 "
        "{%0,%1,%2,%3}, {%4,%5,%6,%7}, {%8,%9}, {%0,%1,%2,%3};"
        : "+f"(d[0]), "+f"(d[1]), "+f"(d[2]), "+f"(d[3])
        : "r"(a[0]), "r"(a[1]), "r"(a[2]), "r"(a[3]), "r"(b0), "r"(b1));
}

// ---------------------------------------------------------------------------
// Init: packed B fragments for 6 weights + permuted pos-params + Gram.
// ---------------------------------------------------------------------------
__global__ void build_kernel(const float* __restrict__ wg1,
                             const float* __restrict__ wg2,
                             const float* __restrict__ wq,
                             const float* __restrict__ wk,
                             const float* __restrict__ wv,
                             const float* __restrict__ wo,
                             const float* __restrict__ wp,
                             const float* __restrict__ bp,
                             const float* __restrict__ gp,
                             const float* __restrict__ betap)
{
    const int t = threadIdx.x;
    if (blockIdx.x < 24) {
        const int e = blockIdx.x * 256 + t;
        const int lane = e & 31;
        const int kt   = (e >> 5) & 3;
        const int j    = (e >> 7) & 7;
        const int wi   = e >> 10;
        const float* Wt[6] = { wg1, wg2, wq, wk, wv, wo };
        const float* W = Wt[wi];
        const int n  = 8 * j + (lane >> 2);
        const int k0 = 16 * kt + 2 * (lane & 3);
        u32 h0, l0, h1, l1;
        bsplit2(W[k0 * 64 + n],       W[(k0 + 1) * 64 + n], h0, l0);
        bsplit2(W[(k0 + 8) * 64 + n], W[(k0 + 9) * 64 + n], h1, l1);
        g_bfragP[e] = make_uint4(h0, h1, l0, l1);
    } else {
        if (t < 64) {
            const int p = t;
            const int kt = p >> 4, q = (p >> 2) & 3, i = p & 3;
            const int tc = 16 * kt + ((i < 2) ? (2 * q + i) : (6 + 2 * q + i));
            g_pp[0 * 64 + p] = wp[tc];
            g_pp[1 * 64 + p] = wp[64 + tc];
            g_pp[2 * 64 + p] = wp[128 + tc];
            g_pp[3 * 64 + p] = bp[tc];
            g_pp[4 * 64 + p] = gp[tc];
            g_pp[5 * 64 + p] = betap[tc];
        } else if (t < 84) {
            const int tt = t - 64;
            if (tt < 16) {
                const int a = tt >> 2, b = tt & 3;
                const float* ra = (a < 3) ? (wp + a * 64) : bp;
                const float* rb = (b < 3) ? (wp + b * 64) : bp;
                float s = 0.f;
                for (int c = 0; c < 64; c++) s += ra[c] * rb[c];
                g_gram[tt] = s;
            } else {
                const int a = tt - 16;
                const float* ra = (a < 3) ? (wp + a * 64) : bp;
                float s = 0.f;
                for (int c = 0; c < 64; c++) s += ra[c];
                g_gram[tt] = s;
            }
        }
    }
}

// ---------------------------------------------------------------------------
// Kernel A: q/k/v via mma.sync bf16-split; K-PERMUTED output layout.
// ---------------------------------------------------------------------------
__global__ __launch_bounds__(128, 4) void qkv_mma_kernel(
    const float* __restrict__ feat, int N,
    const float* __restrict__ bq, const float* __restrict__ bk,
    const float* __restrict__ bv)
{
    const int t = threadIdx.x;
    const int lane = t & 31;
    const int warp = t >> 5;
    const int qd = lane & 3;
    const int base = 2 * qd;
    const int r1 = lane >> 2;

    const int row0 = (blockIdx.x * 4 + warp) * 16;
    const int rowA = row0 + r1;
    const int rowB = row0 + r1 + 8;
    const int rowAc = (rowA < N) ? rowA : N - 1;
    const int rowBc = (rowB < N) ? rowB : N - 1;

    u32 aHi[16], aLo[16];
#pragma unroll
    for (int m = 0; m < 8; m++) {
        const int c = 8 * m + base;
        const float2 fA = *(const float2*)(feat + rowAc * 64 + c);
        const float2 fB = *(const float2*)(feat + rowBc * 64 + c);
        const int kt = m >> 1;
        const int ro = (m & 1) << 1;
        bsplit2(fA.x, fA.y, aHi[kt * 4 + ro],     aLo[kt * 4 + ro]);
        bsplit2(fB.x, fB.y, aHi[kt * 4 + ro + 1], aLo[kt * 4 + ro + 1]);
    }

    const float* Bs[3] = { bq, bk, bv };
    float* Gs[3] = { g_q, g_k, g_v };
#pragma unroll 1
    for (int wi = 0; wi < 3; wi++) {
        const uint4* fr = g_bfragP + (2 + wi) * 1024;
        float d[8][4];
#pragma unroll
        for (int j = 0; j < 8; j++)
#pragma unroll
            for (int i = 0; i < 4; i++) d[j][i] = 0.f;
#pragma unroll
        for (int kt = 0; kt < 4; kt++) {
#pragma unroll
            for (int j = 0; j < 8; j++) {
                const uint4 e = __ldg(&fr[j * 128 + kt * 32 + lane]);
                mma16816(d[j], &aHi[kt * 4], e.x, e.y);
                mma16816(d[j], &aLo[kt * 4], e.x, e.y);
                mma16816(d[j], &aHi[kt * 4], e.z, e.w);
            }
        }
        float* G = Gs[wi];
        const float* B = Bs[wi];
#pragma unroll
        for (int j = 0; j < 8; j++) {
            const float2 b2 = __ldg((const float2*)(B + 8 * j + base));
            const int P = 16 * (j >> 1) + 4 * qd + ((j & 1) << 1);
            if (rowA < N)
                *(float2*)(G + rowA * 64 + P) =
                    make_float2(d[j][0] + b2.x, d[j][1] + b2.y);
            if (rowB < N)
                *(float2*)(G + rowB * 64 + P) =
                    make_float2(d[j][2] + b2.x, d[j][3] + b2.y);
        }
    }
}

// ---------------------------------------------------------------------------
// Kernel B: one warp per point (round-10 structure); softmax output to
// g_mout (final projection moved to outproj kernel). 6 CTA/SM.
// ---------------------------------------------------------------------------
#define GVS 66
#define LWS 66

__global__ __launch_bounds__(128, 6) void pt_mma_kernel(
    const float* __restrict__ points,
    const int* __restrict__ nbr, int N,
    const float* __restrict__ bg1, const float* __restrict__ gg,
    const float* __restrict__ betag)
{
    __shared__ float gvs[4 * 16 * GVS];   // 16896 B
    __shared__ float lw[4][16][LWS];      // 16896 B
    __shared__ float spp[404];            // 1616 B: pp (384) + gram (20)

    const int t = threadIdx.x;
    const int lane = t & 31;
    const int warp = t >> 5;

    for (int i = t; i < 404; i += 128)
        spp[i] = (i < 384) ? g_pp[i] : g_gram[i - 384];
    __syncthreads();
    const float* sM = spp + 384;

    int n = blockIdx.x * 4 + warp;
    if (n >= N) n = N - 1;

    const int qd = lane & 3;
    const int base = 2 * qd;
    const int r1 = lane >> 2;
    float* mygv = gvs + warp * 16 * GVS;

    const int id1 = __ldg(&nbr[n * 16 + r1]);
    const int id2 = __ldg(&nbr[n * 16 + r1 + 8]);
    const float px = __ldg(&points[n * 3 + 0]);
    const float py = __ldg(&points[n * 3 + 1]);
    const float pz = __ldg(&points[n * 3 + 2]);
    const float rx1 = __ldg(&points[id1 * 3 + 0]) - px;
    const float ry1 = __ldg(&points[id1 * 3 + 1]) - py;
    const float rz1 = __ldg(&points[id1 * 3 + 2]) - pz;
    const float rx2 = __ldg(&points[id2 * 3 + 0]) - px;
    const float ry2 = __ldg(&points[id2 * 3 + 1]) - py;
    const float rz2 = __ldg(&points[id2 * 3 + 2]) - pz;

    float mean1, inv1, mean2, inv2;
    {
        const float s1 = fmaf(rx1, sM[16], fmaf(ry1, sM[17], fmaf(rz1, sM[18], sM[19])));
        const float tx = fmaf(rx1, sM[0],  fmaf(ry1, sM[1],  fmaf(rz1, sM[2],  sM[3])));
        const float ty = fmaf(rx1, sM[4],  fmaf(ry1, sM[5],  fmaf(rz1, sM[6],  sM[7])));
        const float tz = fmaf(rx1, sM[8],  fmaf(ry1, sM[9],  fmaf(rz1, sM[10], sM[11])));
        const float tw = fmaf(rx1, sM[12], fmaf(ry1, sM[13], fmaf(rz1, sM[14], sM[15])));
        const float s2 = fmaf(rx1, tx, fmaf(ry1, ty, fmaf(rz1, tz, tw)));
        mean1 = s1 * 0.015625f;
        inv1 = rsqrtf(s2 * 0.015625f - mean1 * mean1 + LN_EPS);
    }
    {
        const float s1 = fmaf(rx2, sM[16], fmaf(ry2, sM[17], fmaf(rz2, sM[18], sM[19])));
        const float tx = fmaf(rx2, sM[0],  fmaf(ry2, sM[1],  fmaf(rz2, sM[2],  sM[3])));
        const float ty = fmaf(rx2, sM[4],  fmaf(ry2, sM[5],  fmaf(rz2, sM[6],  sM[7])));
        const float tz = fmaf(rx2, sM[8],  fmaf(ry2, sM[9],  fmaf(rz2, sM[10], sM[11])));
        const float tw = fmaf(rx2, sM[12], fmaf(ry2, sM[13], fmaf(rz2, sM[14], sM[15])));
        const float s2 = fmaf(rx2, tx, fmaf(ry2, ty, fmaf(rz2, tz, tw)));
        mean2 = s1 * 0.015625f;
        inv2 = rsqrtf(s2 * 0.015625f - mean2 * mean2 + LN_EPS);
    }

    // ---- gather (float4, permuted) + positional LN/relu -> A frags; gv -> SMEM
    u32 aHi[16], aLo[16];
#pragma unroll
    for (int kt = 0; kt < 4; kt++) {
        const int pc = 16 * kt + 4 * qd;
        const float4 q4  = *(const float4*)(g_q + n * 64 + pc);
        const float4 k1v = *(const float4*)(g_k + id1 * 64 + pc);
        const float4 k2v = *(const float4*)(g_k + id2 * 64 + pc);
        const float4 v1v = *(const float4*)(g_v + id1 * 64 + pc);
        const float4 v2v = *(const float4*)(g_v + id2 * 64 + pc);
        const float4 wxv = *(const float4*)(spp + 0 * 64 + pc);
        const float4 wyv = *(const float4*)(spp + 1 * 64 + pc);
        const float4 wzv = *(const float4*)(spp + 2 * 64 + pc);
        const float4 bpv = *(const float4*)(spp + 3 * 64 + pc);
        const float4 gpv = *(const float4*)(spp + 4 * 64 + pc);
        const float4 bev = *(const float4*)(spp + 5 * 64 + pc);

        float vA[4], vB[4];
        {
            const float* wx = &wxv.x; const float* wy = &wyv.x;
            const float* wz = &wzv.x; const float* bb = &bpv.x;
            const float* gp2 = &gpv.x; const float* be = &bev.x;
#pragma unroll
            for (int i = 0; i < 4; i++) {
                const float pA = fmaf(rx1, wx[i], fmaf(ry1, wy[i],
                                 fmaf(rz1, wz[i], bb[i])));
                const float pB = fmaf(rx2, wx[i], fmaf(ry2, wy[i],
                                 fmaf(rz2, wz[i], bb[i])));
                vA[i] = fmaxf(fmaf((pA - mean1) * inv1, gp2[i], be[i]), 0.f);
                vB[i] = fmaxf(fmaf((pB - mean2) * inv2, gp2[i], be[i]), 0.f);
            }
        }

        bsplit2(q4.x - k1v.x + vA[0], q4.y - k1v.y + vA[1],
                aHi[kt * 4 + 0], aLo[kt * 4 + 0]);
        bsplit2(q4.x - k2v.x + vB[0], q4.y - k2v.y + vB[1],
                aHi[kt * 4 + 1], aLo[kt * 4 + 1]);
        bsplit2(q4.z - k1v.z + vA[2], q4.w - k1v.w + vA[3],
                aHi[kt * 4 + 2], aLo[kt * 4 + 2]);
        bsplit2(q4.z - k2v.z + vB[2], q4.w - k2v.w + vB[3],
                aHi[kt * 4 + 3], aLo[kt * 4 + 3]);

        *(float2*)(mygv + r1 * GVS + 16 * kt + base) =
            make_float2(v1v.x + vA[0], v1v.y + vA[1]);
        *(float2*)(mygv + (r1 + 8) * GVS + 16 * kt + base) =
            make_float2(v2v.x + vB[0], v2v.y + vB[1]);
        *(float2*)(mygv + r1 * GVS + 16 * kt + 8 + base) =
            make_float2(v1v.z + vA[2], v1v.w + vA[3]);
        *(float2*)(mygv + (r1 + 8) * GVS + 16 * kt + 8 + base) =
            make_float2(v2v.z + vB[2], v2v.w + vB[3]);
    }

    // ---- GEMM1: d = attn @ wg1 ----
    float d[8][4];
#pragma unroll
    for (int j = 0; j < 8; j++)
#pragma unroll
        for (int i = 0; i < 4; i++) d[j][i] = 0.f;
#pragma unroll
    for (int kt = 0; kt < 4; kt++) {
#pragma unroll
        for (int j = 0; j < 8; j++) {
            const uint4 e = __ldg(&g_bfragP[j * 128 + kt * 32 + lane]);
            mma16816(d[j], &aHi[kt * 4], e.x, e.y);
            mma16816(d[j], &aLo[kt * 4], e.x, e.y);
            mma16816(d[j], &aHi[kt * 4], e.z, e.w);
        }
    }

    // ---- LN + relu over rows (4-lane groups) ----
    {
        float s1a = 0.f, s2a = 0.f, s1b = 0.f, s2b = 0.f;
#pragma unroll
        for (int j = 0; j < 8; j++) {
            const float2 bg = __ldg((const float2*)(bg1 + 8 * j + base));
            d[j][0] += bg.x; d[j][1] += bg.y;
            d[j][2] += bg.x; d[j][3] += bg.y;
            s1a += d[j][0] + d[j][1];
            s2a += d[j][0] * d[j][0] + d[j][1] * d[j][1];
            s1b += d[j][2] + d[j][3];
            s2b += d[j][2] * d[j][2] + d[j][3] * d[j][3];
        }
#pragma unroll
        for (int off = 1; off <= 2; off <<= 1) {
            s1a += __shfl_xor_sync(0xffffffffu, s1a, off);
            s2a += __shfl_xor_sync(0xffffffffu, s2a, off);
            s1b += __shfl_xor_sync(0xffffffffu, s1b, off);
            s2b += __shfl_xor_sync(0xffffffffu, s2b, off);
        }
        const float m1 = s1a * 0.015625f;
        const float i1 = rsqrtf(s2a * 0.015625f - m1 * m1 + LN_EPS);
        const float m2 = s1b * 0.015625f;
        const float i2 = rsqrtf(s2b * 0.015625f - m2 * m2 + LN_EPS);
#pragma unroll
        for (int j = 0; j < 8; j++) {
            const int c = 8 * j + base;
            const float2 gA = __ldg((const float2*)(gg + c));
            const float2 bA = __ldg((const float2*)(betag + c));
            d[j][0] = fmaxf(fmaf((d[j][0] - m1) * i1, gA.x, bA.x), 0.f);
            d[j][1] = fmaxf(fmaf((d[j][1] - m1) * i1, gA.y, bA.y), 0.f);
            d[j][2] = fmaxf(fmaf((d[j][2] - m2) * i2, gA.x, bA.x), 0.f);
            d[j][3] = fmaxf(fmaf((d[j][3] - m2) * i2, gA.y, bA.y), 0.f);
        }
    }

    // ---- repack h into A fragments ----
#pragma unroll
    for (int kt = 0; kt < 4; kt++) {
        bsplit2(d[2 * kt][0],     d[2 * kt][1],     aHi[kt * 4 + 0], aLo[kt * 4 + 0]);
        bsplit2(d[2 * kt][2],     d[2 * kt][3],     aHi[kt * 4 + 1], aLo[kt * 4 + 1]);
        bsplit2(d[2 * kt + 1][0], d[2 * kt + 1][1], aHi[kt * 4 + 2], aLo[kt * 4 + 2]);
        bsplit2(d[2 * kt + 1][2], d[2 * kt + 1][3], aHi[kt * 4 + 3], aLo[kt * 4 + 3]);
    }

    // ---- GEMM2: logits = h @ wg2 (bg2 cancels in softmax) ----
#pragma unroll
    for (int j = 0; j < 8; j++)
#pragma unroll
        for (int i = 0; i < 4; i++) d[j][i] = 0.f;
#pragma unroll
    for (int kt = 0; kt < 4; kt++) {
#pragma unroll
        for (int j = 0; j < 8; j++) {
            const uint4 e = __ldg(&g_bfragP[1024 + j * 128 + kt * 32 + lane]);
            mma16816(d[j], &aHi[kt * 4], e.x, e.y);
            mma16816(d[j], &aLo[kt * 4], e.x, e.y);
            mma16816(d[j], &aHi[kt * 4], e.z, e.w);
        }
    }

    // ---- stage logits to smem; column softmax; write g_mout ----
#pragma unroll
    for (int j = 0; j < 8; j++) {
        *(float2*)&lw[warp][r1][8 * j + base]     = make_float2(d[j][0], d[j][1]);
        *(float2*)&lw[warp][r1 + 8][8 * j + base] = make_float2(d[j][2], d[j][3]);
    }
    __syncwarp();
#pragma unroll
    for (int cc = 0; cc < 2; cc++) {
        const int c = lane + 32 * cc;
        float mx = -3.4e38f;
#pragma unroll
        for (int k = 0; k < 16; k++) mx = fmaxf(mx, lw[warp][k][c]);
        float s = 0.f, o = 0.f;
#pragma unroll
        for (int k = 0; k < 16; k++) {
            const float e = __expf(lw[warp][k][c] - mx);
            s += e;
            o = fmaf(e, mygv[k * GVS + c], o);
        }
        g_mout[n * 64 + c] = __fdividef(o, s);
    }
}

// ---------------------------------------------------------------------------
// Kernel C: out = mout @ wo + bo + feat (residual). qkv-style batched GEMM.
// ---------------------------------------------------------------------------
__global__ __launch_bounds__(128, 4) void outproj_mma_kernel(
    const float* __restrict__ feat, int N,
    const float* __restrict__ bo, float* __restrict__ out)
{
    const int t = threadIdx.x;
    const int lane = t & 31;
    const int warp = t >> 5;
    const int base = 2 * (lane & 3);
    const int r1 = lane >> 2;

    const int row0 = (blockIdx.x * 4 + warp) * 16;
    const int rowA = row0 + r1;
    const int rowB = row0 + r1 + 8;
    const int rowAc = (rowA < N) ? rowA : N - 1;
    const int rowBc = (rowB < N) ? rowB : N - 1;

    u32 aHi[16], aLo[16];
#pragma unroll
    for (int m = 0; m < 8; m++) {
        const int c = 8 * m + base;
        const float2 fA = *(const float2*)(g_mout + rowAc * 64 + c);
        const float2 fB = *(const float2*)(g_mout + rowBc * 64 + c);
        const int kt = m >> 1;
        const int ro = (m & 1) << 1;
        bsplit2(fA.x, fA.y, aHi[kt * 4 + ro],     aLo[kt * 4 + ro]);
        bsplit2(fB.x, fB.y, aHi[kt * 4 + ro + 1], aLo[kt * 4 + ro + 1]);
    }

    float d[8][4];
#pragma unroll
    for (int j = 0; j < 8; j++)
#pragma unroll
        for (int i = 0; i < 4; i++) d[j][i] = 0.f;
#pragma unroll
    for (int kt = 0; kt < 4; kt++) {
#pragma unroll
        for (int j = 0; j < 8; j++) {
            const uint4 e = __ldg(&g_bfragP[5120 + j * 128 + kt * 32 + lane]);
            mma16816(d[j], &aHi[kt * 4], e.x, e.y);
            mma16816(d[j], &aLo[kt * 4], e.x, e.y);
            mma16816(d[j], &aHi[kt * 4], e.z, e.w);
        }
    }

#pragma unroll
    for (int j = 0; j < 8; j++) {
        const int c = 8 * j + base;
        const float2 b2 = __ldg((const float2*)(bo + c));
        if (rowA < N) {
            const float2 f2 = *(const float2*)(feat + rowA * 64 + c);
            *(float2*)(out + rowA * 64 + c) =
                make_float2(d[j][0] + b2.x + f2.x, d[j][1] + b2.y + f2.y);
        }
        if (rowB < N) {
            const float2 f2 = *(const float2*)(feat + rowB * 64 + c);
            *(float2*)(out + rowB * 64 + c) =
                make_float2(d[j][2] + b2.x + f2.x, d[j][3] + b2.y + f2.y);
        }
    }
}

// ---------------------------------------------------------------------------
extern "C" void kernel_launch(void* const* d_in, const int* in_sizes, int n_in,
                              void* d_out, int out_size)
{
    const float* points = (const float*)d_in[0];
    const float* feat   = (const float*)d_in[1];
    const int*   nbr    = (const int*)  d_in[2];
    const float* wq     = (const float*)d_in[3];
    const float* bq     = (const float*)d_in[4];
    const float* wk     = (const float*)d_in[5];
    const float* bk     = (const float*)d_in[6];
    const float* wv     = (const float*)d_in[7];
    const float* bv     = (const float*)d_in[8];
    const float* wp     = (const float*)d_in[9];
    const float* bp     = (const float*)d_in[10];
    const float* gp     = (const float*)d_in[11];
    const float* betap  = (const float*)d_in[12];
    const float* wg1    = (const float*)d_in[13];
    const float* bg1    = (const float*)d_in[14];
    const float* gg     = (const float*)d_in[15];
    const float* betag  = (const float*)d_in[16];
    const float* wg2    = (const float*)d_in[17];
    const float* bg2    = (const float*)d_in[18];
    const float* wo     = (const float*)d_in[19];
    const float* bo     = (const float*)d_in[20];
    float* out = (float*)d_out;
    (void)bg2;

    const int N = in_sizes[0] / 3;

    build_kernel<<<25, 256>>>(wg1, wg2, wq, wk, wv, wo, wp, bp, gp, betap);
    qkv_mma_kernel<<<(N + 63) / 64, 128>>>(feat, N, bq, bk, bv);
    pt_mma_kernel<<<(N + 3) / 4, 128>>>(points, nbr, N, bg1, gg, betag);
    outproj_mma_kernel<<<(N + 63) / 64, 128>>>(feat, N, bo, out);
}